// round 14
// baseline (speedup 1.0000x reference)
#include <cuda_runtime.h>
#include <stdint.h>

// R13 skeleton (best: 77.2us) + smem bloom prefilter in the PROVEN shape:
// one int4-group per thread (no serial per-thread loops), 1024-thr CTAs to
// amortize the 32KB bloom copy, branchless 4-way LDS tests, conditional
// global probes only for ~32% of keys. Inputs are int32 (JAX x64 disabled);
// triple key (h*15000+r)*15000+t wraps in int32 == uint32 arithmetic.
#define QT_LOG2 19
#define QT_SIZE (1u << QT_LOG2)
#define QT_MASK (QT_SIZE - 1u)
#define EMPTY64 0xFFFFFFFFFFFFFFFFull
#define N_ENT 15000u
#define MAX_Q (1 << 17)

#define BLOOM_LOG2 18
#define BLOOM_BITS (1u << BLOOM_LOG2)
#define BLOOM_WORDS (BLOOM_BITS / 32)    // 8192 words = 32KB

__device__ unsigned long long g_qtable[QT_SIZE];      // 4MB key table
__device__ uint32_t g_bloom[BLOOM_WORDS];             // 32KB bloom
__device__ uint32_t g_found[QT_SIZE / 32];            // 64KB found bitmap
__device__ int g_qslot[MAX_Q];

__device__ __forceinline__ uint32_t make_key(uint32_t h, uint32_t r, uint32_t t) {
    return (h * N_ENT + r) * N_ENT + t;   // wraps mod 2^32 == int32 reference
}

// One Fibonacci multiply feeds both table slot and bloom bit.
__device__ __forceinline__ uint32_t fib(uint32_t key) { return key * 2654435769u; }
__device__ __forceinline__ uint32_t slot_of(uint32_t p) { return p >> (32 - QT_LOG2); }
__device__ __forceinline__ uint32_t bloombit_of(uint32_t p) { return p >> (32 - BLOOM_LOG2); }

__device__ __forceinline__ unsigned long long ld_cg64(const unsigned long long* p) {
    unsigned long long v;
    asm volatile("ld.global.cg.u64 %0, [%1];" : "=l"(v) : "l"(p));
    return v;
}
__device__ __forceinline__ int4 ld_cs128(const int4* p) {
    int4 v;
    asm volatile("ld.global.cs.v4.s32 {%0,%1,%2,%3}, [%4];"
                 : "=r"(v.x), "=r"(v.y), "=r"(v.z), "=r"(v.w) : "l"(p));
    return v;
}
__device__ __forceinline__ int ld_cs32(const int* p) {
    int v;
    asm volatile("ld.global.cs.s32 %0, [%1];" : "=r"(v) : "l"(p));
    return v;
}

// ---- Pass A: clear table + bloom + bitmap ----
__global__ void clear_kernel() {
    uint32_t tid = blockIdx.x * blockDim.x + threadIdx.x;
    uint32_t stride = gridDim.x * blockDim.x;
    ulonglong2* p = reinterpret_cast<ulonglong2*>(g_qtable);
    ulonglong2 v; v.x = EMPTY64; v.y = EMPTY64;
    for (uint32_t i = tid; i < QT_SIZE / 2; i += stride) p[i] = v;
    for (uint32_t i = tid; i < QT_SIZE / 32; i += stride) g_found[i] = 0u;
    for (uint32_t i = tid; i < BLOOM_WORDS; i += stride) g_bloom[i] = 0u;
}

// ---- Pass B: insert query keys, set bloom bit, record slot ----
__global__ void insert_queries_kernel(const int* __restrict__ heads,
                                      const int* __restrict__ rels,
                                      const int* __restrict__ tails, int q) {
    int i = blockIdx.x * blockDim.x + threadIdx.x;
    if (i >= q) return;
    uint32_t key = make_key((uint32_t)heads[i], (uint32_t)rels[i], (uint32_t)tails[i]);
    uint32_t p = fib(key);
    uint32_t b = bloombit_of(p);
    atomicOr(&g_bloom[b >> 5], 1u << (b & 31));
    uint32_t slot = slot_of(p);
    while (true) {
        unsigned long long v = ld_cg64(&g_qtable[slot]);
        if (v != EMPTY64 && (uint32_t)v == key) break;      // dup
        if (v == EMPTY64) {
            unsigned long long prev =
                atomicCAS(&g_qtable[slot], EMPTY64, (unsigned long long)key);
            if (prev == EMPTY64 || (uint32_t)prev == key) break;
        }
        slot = (slot + 1) & QT_MASK;
    }
    g_qslot[i] = (int)slot;
}

// ---- Pass C: stream data; smem bloom prefilter + exact probe ----
__device__ __forceinline__ void probe_mark(uint32_t key) {
    uint32_t slot = slot_of(fib(key));
    unsigned long long v = ld_cg64(&g_qtable[slot]);
    while (true) {
        if (v == EMPTY64) return;               // bloom false positive
        if ((uint32_t)v == key) {
            atomicOr(&g_found[slot >> 5], 1u << (slot & 31));
            return;
        }
        slot = (slot + 1) & QT_MASK;
        v = ld_cg64(&g_qtable[slot]);
    }
}

__global__ void __launch_bounds__(1024) mark_kernel(const int* __restrict__ data,
                                                    int n4, int n) {
    __shared__ uint32_t s_bloom[BLOOM_WORDS];   // 32KB
    for (uint32_t j = threadIdx.x; j < BLOOM_WORDS; j += 1024)
        s_bloom[j] = g_bloom[j];
    __syncthreads();

    int i = blockIdx.x * 1024 + threadIdx.x;
    if (i < n4) {
        const int4* d0 = reinterpret_cast<const int4*>(data);
        const int4* d1 = reinterpret_cast<const int4*>(data + n);
        const int4* d2 = reinterpret_cast<const int4*>(data + 2 * n);
        int4 h = ld_cs128(&d0[i]);
        int4 r = ld_cs128(&d1[i]);
        int4 t = ld_cs128(&d2[i]);
        uint32_t k0 = make_key((uint32_t)h.x, (uint32_t)r.x, (uint32_t)t.x);
        uint32_t k1 = make_key((uint32_t)h.y, (uint32_t)r.y, (uint32_t)t.y);
        uint32_t k2 = make_key((uint32_t)h.z, (uint32_t)r.z, (uint32_t)t.z);
        uint32_t k3 = make_key((uint32_t)h.w, (uint32_t)r.w, (uint32_t)t.w);
        uint32_t b0 = bloombit_of(fib(k0)), b1 = bloombit_of(fib(k1));
        uint32_t b2 = bloombit_of(fib(k2)), b3 = bloombit_of(fib(k3));
        // 4 independent LDS in flight, then bit tests
        uint32_t w0 = s_bloom[b0 >> 5], w1 = s_bloom[b1 >> 5];
        uint32_t w2 = s_bloom[b2 >> 5], w3 = s_bloom[b3 >> 5];
        if ((w0 >> (b0 & 31)) & 1u) probe_mark(k0);
        if ((w1 >> (b1 & 31)) & 1u) probe_mark(k1);
        if ((w2 >> (b2 & 31)) & 1u) probe_mark(k2);
        if ((w3 >> (b3 & 31)) & 1u) probe_mark(k3);
    }
    // tail (n % 4 != 0): at most 3 keys handled by the first threads
    int tail_start = n4 * 4;
    if (i < n - tail_start) {
        int ti = tail_start + i;
        probe_mark(make_key((uint32_t)ld_cs32(&data[ti]),
                            (uint32_t)ld_cs32(&data[n + ti]),
                            (uint32_t)ld_cs32(&data[2 * n + ti])));
    }
}

// ---- Pass D: resolve via recorded slot + L1-resident bitmap ----
__global__ void resolve_kernel(float* __restrict__ out, int q) {
    int i = blockIdx.x * blockDim.x + threadIdx.x;
    if (i >= q) return;
    uint32_t slot = (uint32_t)g_qslot[i];
    uint32_t w = g_found[slot >> 5];
    out[i] = ((w >> (slot & 31)) & 1u) ? 5.0f : -5.0f;
}

extern "C" void kernel_launch(void* const* d_in, const int* in_sizes, int n_in,
                              void* d_out, int out_size) {
    const int* heads = (const int*)d_in[0];
    const int* rels  = (const int*)d_in[1];
    const int* tails = (const int*)d_in[2];
    const int* data  = (const int*)d_in[3];
    float* out = (float*)d_out;

    const int q = in_sizes[0];
    const int n = in_sizes[3] / 3;
    const int n4 = n >> 2;
    const int threads = 256;

    // A: clear 4MB qtable + 32KB bloom + 64KB bitmap
    clear_kernel<<<148 * 4, threads>>>();
    // B: insert query keys (bloom + table + slot record)
    insert_queries_kernel<<<(q + threads - 1) / threads, threads>>>(heads, rels, tails, q);
    // C: one thread per 4 keys; smem-bloom prefilter, conditional probes
    mark_kernel<<<(n4 + 1023) / 1024, 1024>>>(data, n4, n);
    // D: write +/-5 per query from slot + bitmap
    resolve_kernel<<<(q + threads - 1) / threads, threads>>>(out, q);
}